// round 15
// baseline (speedup 1.0000x reference)
#include <cuda_runtime.h>
#include <math.h>
#include <stdint.h>

#define NMAX 20000
#define EMAX 200000

// ---------------- scratch (static __device__; no cudaMalloc) ----------------
__device__ float g_pre[NMAX * 512];
__device__ float g_selfx[NMAX * 512];
__device__ float g_acc[NMAX * 512];
__device__ float g_xg[NMAX * 512];
__device__ float g_h[NMAX * 256];
__device__ float g_adst[NMAX * 32];
__device__ float g_ws1ab[128 * 32];
__device__ float g_hf[EMAX * 32];
__device__ float g_hs[EMAX * 32];

// ---------------- helpers ----------------------------------------------------
__device__ __forceinline__ float sspf(float v) {
    float sp = (v > 0.f) ? (v + log1pf(expf(-v))) : log1pf(expf(v));
    return sp - 0.693147180559945309f;
}
__device__ __forceinline__ float siluf(float v) {
    return v / (1.f + expf(-v));
}
__device__ __forceinline__ void red_add_v4(float* addr, float a, float b, float c, float d) {
    asm volatile("red.global.add.v4.f32 [%0], {%1,%2,%3,%4};"
                 :: "l"(addr), "f"(a), "f"(b), "f"(c), "f"(d) : "memory");
}
__device__ __forceinline__ uint32_t f2tf32(float f) {
    uint32_t u;
    asm("cvt.rna.tf32.f32 %0, %1;" : "=r"(u) : "f"(f));
    return u;
}
__device__ __forceinline__ void mma_tf32(float c[4], const uint32_t a[4],
                                         uint32_t b0, uint32_t b1) {
    asm volatile(
        "mma.sync.aligned.m16n8k8.row.col.f32.tf32.tf32.f32 "
        "{%0,%1,%2,%3}, {%4,%5,%6,%7}, {%8,%9}, {%0,%1,%2,%3};"
        : "+f"(c[0]), "+f"(c[1]), "+f"(c[2]), "+f"(c[3])
        : "r"(a[0]), "r"(a[1]), "r"(a[2]), "r"(a[3]), "r"(b0), "r"(b1));
}

// ---------------- ws1ab = W_s1[0:128] + W_s1[128:256] -----------------------
__global__ void k_prep(const float* __restrict__ W_s1, float* __restrict__ ws1ab) {
    int i = blockIdx.x * blockDim.x + threadIdx.x;
    if (i < 128 * 32) ws1ab[i] = W_s1[i] + W_s1[128 * 32 + i];
}

// ---------------- irrep_linear via tf32 mma (validated R8) -------------------
#define XSS 516
#define WSS 132
#define SM_IRREP_MMA ((32 * XSS + 2 * 32 * WSS) * 4)
__global__ void __launch_bounds__(256, 2) k_irrep(
    const float* __restrict__ X, const float* __restrict__ W0,
    const float* __restrict__ b0, const float* __restrict__ W1,
    float* __restrict__ Y, float* __restrict__ Y2,
    const float* __restrict__ resid, int nRows)
{
    extern __shared__ float smf[];
    float* Xs = smf;                                  // 32*516
    uint32_t* sW0 = (uint32_t*)(Xs + 32 * XSS);       // 32*132
    uint32_t* sW1 = sW0 + 32 * WSS;                   // 32*132
    const int tid = threadIdx.x;
    const int row0 = blockIdx.x * 32;
    const int warp = tid >> 5, lane = tid & 31;
    const int g = lane >> 2, t4 = lane & 3;
    const int kind = warp >> 1;
    const int nb = (warp & 1) * 16;

    for (int i = tid; i < 32 * 512; i += 256) {
        int r = i >> 9, c = i & 511;
        int gr = row0 + r;
        Xs[r * XSS + c] = (gr < nRows) ? X[(size_t)gr * 512 + c] : 0.f;
    }

    float acc[16][4];
#pragma unroll
    for (int i = 0; i < 16; i++)
#pragma unroll
        for (int j = 0; j < 4; j++) acc[i][j] = 0.f;

    for (int kc = 0; kc < 4; kc++) {
        __syncthreads();
        for (int i = tid; i < 32 * 128; i += 256) {
            int k = i >> 7, v = i & 127;
            sW0[k * WSS + v] = f2tf32(W0[(size_t)(kc * 32 + k) * 128 + v]);
            sW1[k * WSS + v] = f2tf32(W1[(size_t)(kc * 32 + k) * 128 + v]);
        }
        __syncthreads();
        const uint32_t* sB = (kind == 0) ? sW0 : sW1;
#pragma unroll
        for (int k8 = 0; k8 < 4; k8++) {
            const int kg = kc * 32 + k8 * 8;
            uint32_t a[4];
            if (kind == 0) {
                a[0] = f2tf32(Xs[(nb + g) * XSS + kg + t4]);
                a[1] = f2tf32(Xs[(nb + g + 8) * XSS + kg + t4]);
                a[2] = f2tf32(Xs[(nb + g) * XSS + kg + t4 + 4]);
                a[3] = f2tf32(Xs[(nb + g + 8) * XSS + kg + t4 + 4]);
            } else {
                const int c = kind - 1;
                a[0] = f2tf32(Xs[(nb + g) * XSS + 128 + (kg + t4) * 3 + c]);
                a[1] = f2tf32(Xs[(nb + g + 8) * XSS + 128 + (kg + t4) * 3 + c]);
                a[2] = f2tf32(Xs[(nb + g) * XSS + 128 + (kg + t4 + 4) * 3 + c]);
                a[3] = f2tf32(Xs[(nb + g + 8) * XSS + 128 + (kg + t4 + 4) * 3 + c]);
            }
#pragma unroll
            for (int nt = 0; nt < 16; nt++) {
                uint32_t br0 = sB[(k8 * 8 + t4) * WSS + nt * 8 + g];
                uint32_t br1 = sB[(k8 * 8 + t4 + 4) * WSS + nt * 8 + g];
                mma_tf32(acc[nt], a, br0, br1);
            }
        }
    }
    __syncthreads();
#pragma unroll
    for (int nt = 0; nt < 16; nt++) {
        const int c0 = nt * 8 + 2 * t4;
        const int n0 = nb + g, n1 = nb + g + 8;
        if (kind == 0) {
            Xs[n0 * XSS + c0]     = acc[nt][0];
            Xs[n0 * XSS + c0 + 1] = acc[nt][1];
            Xs[n1 * XSS + c0]     = acc[nt][2];
            Xs[n1 * XSS + c0 + 1] = acc[nt][3];
        } else {
            const int cc = kind - 1;
            Xs[n0 * XSS + 128 + c0 * 3 + cc]       = acc[nt][0];
            Xs[n0 * XSS + 128 + (c0 + 1) * 3 + cc] = acc[nt][1];
            Xs[n1 * XSS + 128 + c0 * 3 + cc]       = acc[nt][2];
            Xs[n1 * XSS + 128 + (c0 + 1) * 3 + cc] = acc[nt][3];
        }
    }
    __syncthreads();
    for (int i = tid; i < 32 * 128; i += 256) {
        int r = i >> 7, c = (i & 127) * 4;
        int n = row0 + r;
        if (n >= nRows) continue;
        size_t base = (size_t)n * 512 + c;
        float4 v = *reinterpret_cast<float4*>(&Xs[r * XSS + c]);
        if (c < 128) {
            float4 bb = *reinterpret_cast<const float4*>(&b0[c]);
            v.x += bb.x; v.y += bb.y; v.z += bb.z; v.w += bb.w;
        }
        if (resid) {
            float4 rr = *reinterpret_cast<const float4*>(&resid[base]);
            v.x += rr.x; v.y += rr.y; v.z += rr.z; v.w += rr.w;
        }
        *reinterpret_cast<float4*>(&Y[base]) = v;
        if (Y2) *reinterpret_cast<float4*>(&Y2[base]) = v;
    }
}

// ---------------- a_dst = p0 @ ws1ab ----------------------------------------
__global__ void __launch_bounds__(256) k_adst(
    const float* __restrict__ pre, const float* __restrict__ ws1ab,
    float* __restrict__ adst, int nRows)
{
    __shared__ float p0s[8 * 128];
    __shared__ float ws[128 * 32];
    const int tid = threadIdx.x;
    const int row0 = blockIdx.x * 8;
    for (int i = tid; i < 128 * 32; i += 256) ws[i] = ws1ab[i];
    for (int i = tid; i < 8 * 128; i += 256) {
        int r = i >> 7, c = i & 127;
        int gr = row0 + r;
        p0s[i] = (gr < nRows) ? pre[(size_t)gr * 512 + c] : 0.f;
    }
    __syncthreads();
    const int h = tid & 31, nl = tid >> 5;
    float acc = 0.f;
#pragma unroll 8
    for (int u = 0; u < 128; u++) acc += p0s[nl * 128 + u] * ws[u * 32 + h];
    int n = row0 + nl;
    if (n < nRows) adst[(size_t)n * 32 + h] = acc;
}

// ---------------- gate GEMM 256x256 with fused znorm / xg --------------------
// mode 0: A staged from x (z computed inline), epi = silu -> Y (h, 256-wide)
// mode 1: A = h (256-wide), epi writes xg (scalar float4 / gated triples)
__global__ void __launch_bounds__(256, 3) k_gemm256(
    const float* __restrict__ X, const float* __restrict__ W,
    const float* __restrict__ b, float* __restrict__ Y,
    const float* __restrict__ xin, int nRows, int mode)
{
    extern __shared__ float sm[];
    float* Xs = sm;             // 32*256
    float* Ws = sm + 32 * 256;  // 32*256
    const int tid = threadIdx.x;
    const int row0 = blockIdx.x * 32;
    for (int i = tid; i < 32 * 256; i += 256) {
        int r = i >> 8, c = i & 255;
        int gr = row0 + r;
        float v = 0.f;
        if (gr < nRows) {
            if (mode == 0) {
                if (c < 128) v = X[(size_t)gr * 512 + c];
                else {
                    const float* p = X + (size_t)gr * 512 + 128 + 3 * (c - 128);
                    v = sqrtf((p[0] * p[0] + p[1] * p[1] + p[2] * p[2]) * (1.f / 3.f));
                }
            } else {
                v = X[(size_t)gr * 256 + c];
            }
        }
        Xs[i] = v;
    }
    const int vg = tid & 63;
    const int ng = tid >> 6;
    float acc[8][4] = {};
    for (int kt = 0; kt < 8; kt++) {
        __syncthreads();
        for (int i = tid; i < 32 * 256; i += 256) {
            int r = i >> 8, c = i & 255;
            Ws[i] = W[(size_t)(kt * 32 + r) * 256 + c];
        }
        __syncthreads();
#pragma unroll
        for (int u4 = 0; u4 < 8; u4++) {
            float4 w0 = *reinterpret_cast<float4*>(&Ws[(u4 * 4 + 0) * 256 + vg * 4]);
            float4 w1 = *reinterpret_cast<float4*>(&Ws[(u4 * 4 + 1) * 256 + vg * 4]);
            float4 w2 = *reinterpret_cast<float4*>(&Ws[(u4 * 4 + 2) * 256 + vg * 4]);
            float4 w3 = *reinterpret_cast<float4*>(&Ws[(u4 * 4 + 3) * 256 + vg * 4]);
#pragma unroll
            for (int ni = 0; ni < 8; ni++) {
                float4 xv = *reinterpret_cast<float4*>(
                    &Xs[(ng * 8 + ni) * 256 + kt * 32 + u4 * 4]);
                acc[ni][0] += xv.x * w0.x + xv.y * w1.x + xv.z * w2.x + xv.w * w3.x;
                acc[ni][1] += xv.x * w0.y + xv.y * w1.y + xv.z * w2.y + xv.w * w3.y;
                acc[ni][2] += xv.x * w0.z + xv.y * w1.z + xv.z * w2.z + xv.w * w3.z;
                acc[ni][3] += xv.x * w0.w + xv.y * w1.w + xv.z * w2.w + xv.w * w3.w;
            }
        }
    }
    float4 bb = *reinterpret_cast<const float4*>(&b[vg * 4]);
    float bv[4] = {bb.x, bb.y, bb.z, bb.w};
#pragma unroll
    for (int ni = 0; ni < 8; ni++) {
        int n = row0 + ng * 8 + ni;
        if (n >= nRows) continue;
        if (mode == 0) {
            float4 o; float* op = (float*)&o;
#pragma unroll
            for (int vi = 0; vi < 4; vi++)
                op[vi] = siluf(acc[ni][vi] + bv[vi]);
            *reinterpret_cast<float4*>(&Y[(size_t)n * 256 + vg * 4]) = o;
        } else {
            size_t base = (size_t)n * 512;
            int c0 = vg * 4;
            if (c0 < 128) {
                float4 o; float* op = (float*)&o;
#pragma unroll
                for (int vi = 0; vi < 4; vi++)
                    op[vi] = acc[ni][vi] + bv[vi];
                *reinterpret_cast<float4*>(&Y[base + c0]) = o;
            } else {
#pragma unroll
                for (int vi = 0; vi < 4; vi++) {
                    int u = c0 + vi - 128;
                    float v = acc[ni][vi] + bv[vi];
                    const float* xp = xin + base + 128 + 3 * u;
                    float* op = Y + base + 128 + 3 * u;
                    op[0] = xp[0] * v;
                    op[1] = xp[1] * v;
                    op[2] = xp[2] * v;
                }
            }
        }
    }
}

// ---------------- k_h: R12 64-edge SIMT version (152 us proven) --------------
#define IPS 132
#define ATS 36
#define KH_SMEM_BYTES ((64 * IPS + 64 * ATS + 128 * 33 + 32 * 33) * 4 + 2 * 64 * 4)
__global__ void __launch_bounds__(256) k_h(
    const float* __restrict__ pre, const float* __restrict__ adst,
    const float* __restrict__ edge_attr, const int* __restrict__ edge_index,
    const float* __restrict__ W_s1, const float* __restrict__ W_f1,
    float* __restrict__ hf_out, float* __restrict__ hs_out, int E)
{
    extern __shared__ float smf[];
    float* sIp  = smf;
    float* sAt  = sIp + 64 * IPS;
    float* sWs  = sAt + 64 * ATS;
    float* sWf  = sWs + 128 * 33;
    int*   sDst = (int*)(sWf + 32 * 33);
    int*   sSrc = sDst + 64;
    const int tid = threadIdx.x;
    const int warp = tid >> 5, lane = tid & 31;
    const int e0 = blockIdx.x * 64;
    const float inv3 = 1.f / 3.f;

    if (tid < 64) {
        int e = e0 + tid;
        sDst[tid] = (e < E) ? edge_index[e] : 0;
        sSrc[tid] = (e < E) ? edge_index[E + e] : 0;
    }
    for (int i = tid; i < 128 * 32; i += 256) {
        int u = i >> 5, c = i & 31;
        sWs[u * 33 + c] = W_s1[256 * 32 + i];
    }
    for (int i = tid; i < 32 * 32; i += 256) {
        int u = i >> 5, c = i & 31;
        sWf[u * 33 + c] = W_f1[i];
    }
    __syncthreads();

#pragma unroll
    for (int s = 0; s < 8; s++) {
        const int el = warp * 8 + s;
        const int e  = e0 + el;
        const int ec = (e < E) ? e : 0;
        const int dst = sDst[el];
        const int src = sSrc[el];
        const float* pd = pre + (size_t)dst * 512 + 128 + 12 * lane;
        const float* ps = pre + (size_t)src * 512 + 128 + 12 * lane;
        float4 d0 = *(const float4*)(pd);
        float4 d1 = *(const float4*)(pd + 4);
        float4 d2 = *(const float4*)(pd + 8);
        float4 s0 = *(const float4*)(ps);
        float4 s1 = *(const float4*)(ps + 4);
        float4 s2 = *(const float4*)(ps + 8);
        float at = edge_attr[(size_t)ec * 32 + lane];
        float4 ipv;
        ipv.x = (d0.x * s0.x + d0.y * s0.y + d0.z * s0.z) * inv3;
        ipv.y = (d0.w * s0.w + d1.x * s1.x + d1.y * s1.y) * inv3;
        ipv.z = (d1.z * s1.z + d1.w * s1.w + d2.x * s2.x) * inv3;
        ipv.w = (d2.y * s2.y + d2.z * s2.z + d2.w * s2.w) * inv3;
        *(float4*)(sIp + el * IPS + 4 * lane) = ipv;
        sAt[el * ATS + lane] = at;
    }
    __syncthreads();

    const int cg = tid & 15, eg = tid >> 4;
    const int c0 = 2 * cg, c1 = c0 + 1;
    const int elb = eg * 4;
    float as0[4], as1[4];
#pragma unroll
    for (int i = 0; i < 4; i++) {
        int dst = sDst[elb + i];
        as0[i] = adst[(size_t)dst * 32 + c0];
        as1[i] = adst[(size_t)dst * 32 + c1];
    }
#pragma unroll 4
    for (int u4 = 0; u4 < 32; u4++) {
        float4 ip0 = *(const float4*)(sIp + (elb + 0) * IPS + u4 * 4);
        float4 ip1 = *(const float4*)(sIp + (elb + 1) * IPS + u4 * 4);
        float4 ip2 = *(const float4*)(sIp + (elb + 2) * IPS + u4 * 4);
        float4 ip3 = *(const float4*)(sIp + (elb + 3) * IPS + u4 * 4);
#pragma unroll
        for (int j = 0; j < 4; j++) {
            int u = u4 * 4 + j;
            float w0 = sWs[u * 33 + c0];
            float w1 = sWs[u * 33 + c1];
            float v0 = (&ip0.x)[j], v1 = (&ip1.x)[j], v2 = (&ip2.x)[j], v3 = (&ip3.x)[j];
            as0[0] += v0 * w0; as1[0] += v0 * w1;
            as0[1] += v1 * w0; as1[1] += v1 * w1;
            as0[2] += v2 * w0; as1[2] += v2 * w1;
            as0[3] += v3 * w0; as1[3] += v3 * w1;
        }
    }
    float af0[4] = {}, af1[4] = {};
#pragma unroll
    for (int u4 = 0; u4 < 8; u4++) {
        float4 a0 = *(const float4*)(sAt + (elb + 0) * ATS + u4 * 4);
        float4 a1 = *(const float4*)(sAt + (elb + 1) * ATS + u4 * 4);
        float4 a2 = *(const float4*)(sAt + (elb + 2) * ATS + u4 * 4);
        float4 a3 = *(const float4*)(sAt + (elb + 3) * ATS + u4 * 4);
#pragma unroll
        for (int j = 0; j < 4; j++) {
            int u = u4 * 4 + j;
            float w0 = sWf[u * 33 + c0];
            float w1 = sWf[u * 33 + c1];
            float v0 = (&a0.x)[j], v1 = (&a1.x)[j], v2 = (&a2.x)[j], v3 = (&a3.x)[j];
            af0[0] += v0 * w0; af1[0] += v0 * w1;
            af0[1] += v1 * w0; af1[1] += v1 * w1;
            af0[2] += v2 * w0; af1[2] += v2 * w1;
            af0[3] += v3 * w0; af1[3] += v3 * w1;
        }
    }
#pragma unroll
    for (int i = 0; i < 4; i++) {
        int e = e0 + elb + i;
        if (e >= E) continue;
        float2 vs; vs.x = sspf(as0[i]); vs.y = sspf(as1[i]);
        float2 vf; vf.x = sspf(af0[i]); vf.y = sspf(af1[i]);
        *reinterpret_cast<float2*>(&hs_out[(size_t)e * 32 + c0]) = vs;
        *reinterpret_cast<float2*>(&hf_out[(size_t)e * 32 + c0]) = vf;
    }
}

// ---------------- k_ws: fused w-GEMM + edge features + segment sum -----------
#define FAS 36
#define FBS 136
#define FWS 520
#define SM_WS ((2 * 32 * FAS + 2 * 32 * FBS + 32 * FWS) * 4 + 2 * 32 * 4)
__global__ void __launch_bounds__(256, 2) k_ws(
    const float* __restrict__ hf, const float* __restrict__ hs,
    const float* __restrict__ Wf2, const float* __restrict__ Ws2,
    const float* __restrict__ selfx, const float* __restrict__ edge_sh,
    const int* __restrict__ edge_index, float* __restrict__ acc_out, int E)
{
    extern __shared__ uint32_t smu[];
    uint32_t* sAf = smu;
    uint32_t* sAs = sAf + 32 * FAS;
    uint32_t* sBf = sAs + 32 * FAS;
    uint32_t* sBs = sBf + 32 * FBS;
    float*    sW  = (float*)(sBs + 32 * FBS);
    int*      sDst = (int*)(sW + 32 * FWS);
    int*      sSrc = sDst + 32;
    const int tid = threadIdx.x;
    const int e0 = blockIdx.x * 32;
    const int warp = tid >> 5, lane = tid & 31;
    const int g = lane >> 2, t4 = lane & 3;
    const int mt = warp >> 2;
    const int ch = warp & 3;
    const int m0 = mt * 16;

    if (tid < 32) {
        int e = e0 + tid;
        sDst[tid] = (e < E) ? edge_index[e] : 0;
        sSrc[tid] = (e < E) ? edge_index[E + e] : 0;
    }
    for (int i = tid; i < 32 * 32; i += 256) {
        int r = i >> 5, c = i & 31;
        int e = e0 + r;
        float vf = (e < E) ? hf[(size_t)e * 32 + c] : 0.f;
        float vs = (e < E) ? hs[(size_t)e * 32 + c] : 0.f;
        sAf[r * FAS + c] = f2tf32(vf);
        sAs[r * FAS + c] = f2tf32(vs);
    }
    __syncthreads();

    uint32_t af[4][4], as_[4][4];
#pragma unroll
    for (int ks = 0; ks < 4; ks++) {
        const int k = ks * 8;
        af[ks][0] = sAf[(m0 + g) * FAS + k + t4];
        af[ks][1] = sAf[(m0 + g + 8) * FAS + k + t4];
        af[ks][2] = sAf[(m0 + g) * FAS + k + t4 + 4];
        af[ks][3] = sAf[(m0 + g + 8) * FAS + k + t4 + 4];
        as_[ks][0] = sAs[(m0 + g) * FAS + k + t4];
        as_[ks][1] = sAs[(m0 + g + 8) * FAS + k + t4];
        as_[ks][2] = sAs[(m0 + g) * FAS + k + t4 + 4];
        as_[ks][3] = sAs[(m0 + g + 8) * FAS + k + t4 + 4];
    }

    for (int sec = 0; sec < 4; sec++) {
        __syncthreads();
        for (int i = tid; i < 32 * 128; i += 256) {
            int k = i >> 7, c = i & 127;
            sBf[k * FBS + c] = f2tf32(Wf2[(size_t)k * 512 + sec * 128 + c]);
            sBs[k * FBS + c] = f2tf32(Ws2[(size_t)k * 512 + sec * 128 + c]);
        }
        __syncthreads();
#pragma unroll
        for (int nt = 0; nt < 4; nt++) {
            float cf[4] = {0.f, 0.f, 0.f, 0.f};
            float cs[4] = {0.f, 0.f, 0.f, 0.f};
            const int nb = ch * 32 + nt * 8 + g;
#pragma unroll
            for (int ks = 0; ks < 4; ks++) {
                const int k = ks * 8;
                uint32_t b0 = sBf[(k + t4) * FBS + nb];
                uint32_t b1 = sBf[(k + t4 + 4) * FBS + nb];
                mma_tf32(cf, af[ks], b0, b1);
                b0 = sBs[(k + t4) * FBS + nb];
                b1 = sBs[(k + t4 + 4) * FBS + nb];
                mma_tf32(cs, as_[ks], b0, b1);
            }
            const int col = sec * 128 + ch * 32 + nt * 8 + 2 * t4;
            sW[(m0 + g) * FWS + col]     = cf[0] * cs[0];
            sW[(m0 + g) * FWS + col + 1] = cf[1] * cs[1];
            sW[(m0 + g + 8) * FWS + col]     = cf[2] * cs[2];
            sW[(m0 + g + 8) * FWS + col + 1] = cf[3] * cs[3];
        }
    }
    __syncthreads();

    const float invs3 = 0.57735026918962576f;
#pragma unroll
    for (int j = 0; j < 4; j++) {
        const int el = warp * 4 + j;
        const int e = e0 + el;
        if (e >= E) continue;
        const int dst = sDst[el];
        const int src = sSrc[el];
        const float* we = sW + el * FWS;
        float4 wq0 = *(const float4*)(we + 0   + 4 * lane);
        float4 wq1 = *(const float4*)(we + 128 + 4 * lane);
        float4 wq2 = *(const float4*)(we + 256 + 4 * lane);
        float4 wq3 = *(const float4*)(we + 384 + 4 * lane);
        float w1[4] = {wq0.x, wq0.y, wq0.z, wq0.w};
        float w2[4] = {wq1.x, wq1.y, wq1.z, wq1.w};
        float w3[4] = {wq2.x, wq2.y, wq2.z, wq2.w};
        float w4[4] = {wq3.x, wq3.y, wq3.z, wq3.w};

        float4 shv = *(const float4*)(edge_sh + (size_t)e * 4);
        const float sh0 = shv.x, sh1x = shv.y, sh1y = shv.z, sh1z = shv.w;
        const float* xs = selfx + (size_t)src * 512;
        float* ao = acc_out + (size_t)dst * 512;
        float4 x0v = *(const float4*)(xs + 4 * lane);
        float4 xv0 = *(const float4*)(xs + 128 + 12 * lane);
        float4 xv1 = *(const float4*)(xs + 128 + 12 * lane + 4);
        float4 xv2 = *(const float4*)(xs + 128 + 12 * lane + 8);
        float x0e[4] = {x0v.x, x0v.y, x0v.z, x0v.w};
        float xa[4] = {xv0.x, xv0.w, xv1.z, xv2.y};
        float xb[4] = {xv0.y, xv1.x, xv1.w, xv2.z};
        float xc[4] = {xv0.z, xv1.y, xv2.x, xv2.w};
        float o0[4], oa[4], ob[4], oc[4];
#pragma unroll
        for (int i = 0; i < 4; i++) {
            o0[i] = w1[i] * x0e[i] * sh0
                  + w4[i] * (xa[i] * sh1x + xb[i] * sh1y + xc[i] * sh1z) * invs3;
            oa[i] = w2[i] * x0e[i] * sh1x + w3[i] * xa[i] * sh0;
            ob[i] = w2[i] * x0e[i] * sh1y + w3[i] * xb[i] * sh0;
            oc[i] = w2[i] * x0e[i] * sh1z + w3[i] * xc[i] * sh0;
        }
        red_add_v4(ao + 4 * lane, o0[0], o0[1], o0[2], o0[3]);
        red_add_v4(ao + 128 + 12 * lane,     oa[0], ob[0], oc[0], oa[1]);
        red_add_v4(ao + 128 + 12 * lane + 4, ob[1], oc[1], oa[2], ob[2]);
        red_add_v4(ao + 128 + 12 * lane + 8, oc[2], oa[3], ob[3], oc[3]);
    }
}

// ---------------- host ------------------------------------------------------
extern "C" void kernel_launch(void* const* d_in, const int* in_sizes, int n_in,
                              void* d_out, int out_size) {
    const float* x         = (const float*)d_in[0];
    const float* edge_sh   = (const float*)d_in[1];
    const float* edge_attr = (const float*)d_in[2];
    const int*   edge_idx  = (const int*)  d_in[3];
    const float* W_pre0 = (const float*)d_in[4];
    const float* b_pre0 = (const float*)d_in[5];
    const float* W_pre1 = (const float*)d_in[6];
    const float* W_nd0  = (const float*)d_in[7];
    const float* b_nd0  = (const float*)d_in[8];
    const float* W_nd1  = (const float*)d_in[9];
    const float* W_g1   = (const float*)d_in[10];
    const float* b_g1   = (const float*)d_in[11];
    const float* W_g2   = (const float*)d_in[12];
    const float* b_g2   = (const float*)d_in[13];
    const float* W_f1   = (const float*)d_in[14];
    const float* W_f2   = (const float*)d_in[15];
    const float* W_s1   = (const float*)d_in[16];
    const float* W_s2   = (const float*)d_in[17];
    const float* W_o0   = (const float*)d_in[18];
    const float* b_o0   = (const float*)d_in[19];
    const float* W_o1   = (const float*)d_in[20];
    float* out = (float*)d_out;

    const int N = in_sizes[0] / 512;
    const int E = in_sizes[3] / 2;

    float *pre, *selfx, *acc, *xg, *h, *adst, *ws1ab, *hf, *hs;
    cudaGetSymbolAddress((void**)&pre,   g_pre);
    cudaGetSymbolAddress((void**)&selfx, g_selfx);
    cudaGetSymbolAddress((void**)&acc,   g_acc);
    cudaGetSymbolAddress((void**)&xg,    g_xg);
    cudaGetSymbolAddress((void**)&h,     g_h);
    cudaGetSymbolAddress((void**)&adst,  g_adst);
    cudaGetSymbolAddress((void**)&ws1ab, g_ws1ab);
    cudaGetSymbolAddress((void**)&hf,    g_hf);
    cudaGetSymbolAddress((void**)&hs,    g_hs);

    const int SM_GEMM = (2 * 32 * 256) * 4;                    // 65536
    const int SM_H    = KH_SMEM_BYTES;                         // 64640
    cudaFuncSetAttribute(k_irrep,   cudaFuncAttributeMaxDynamicSharedMemorySize, SM_IRREP_MMA);
    cudaFuncSetAttribute(k_gemm256, cudaFuncAttributeMaxDynamicSharedMemorySize, SM_GEMM);
    cudaFuncSetAttribute(k_h,       cudaFuncAttributeMaxDynamicSharedMemorySize, SM_H);
    cudaFuncSetAttribute(k_ws,      cudaFuncAttributeMaxDynamicSharedMemorySize, SM_WS);

    const int gIr = (N + 31) / 32;

    // 1) pre = irrep_linear(x, W_pre)
    k_irrep<<<gIr, 256, SM_IRREP_MMA>>>(x, W_pre0, b_pre0, W_pre1, pre, nullptr, nullptr, N);
    // 2) ws1ab, a_dst, edge hidden activations
    k_prep<<<16, 256>>>(W_s1, ws1ab);
    k_adst<<<(N + 7) / 8, 256>>>(pre, ws1ab, adst, N);
    k_h<<<(E + 63) / 64, 256, SM_H>>>(pre, adst, edge_attr, edge_idx, W_s1, W_f1, hf, hs, E);
    // 3) gate path (SIMT, znorm fused into GEMM1 staging, xg fused into GEMM2 epi)
    k_gemm256<<<gIr, 256, SM_GEMM>>>(x, W_g1, b_g1, h, nullptr, N, 0);
    k_gemm256<<<gIr, 256, SM_GEMM>>>(h, W_g2, b_g2, xg, x, N, 1);
    // 4) selfx = irrep_linear(xg, W_nd); dual-write accumulator init
    k_irrep<<<gIr, 256, SM_IRREP_MMA>>>(xg, W_nd0, b_nd0, W_nd1, selfx, acc, nullptr, N);
    // 5) fused w-GEMM + edge features + segment sum into acc
    k_ws<<<(E + 31) / 32, 256, SM_WS>>>(hf, hs, W_f2, W_s2, selfx, edge_sh,
                                        edge_idx, acc, E);
    // 6) out = irrep_linear(acc, W_o) + x
    k_irrep<<<gIr, 256, SM_IRREP_MMA>>>(acc, W_o0, b_o0, W_o1, out, nullptr, x, N);
}

// round 16
// speedup vs baseline: 1.0364x; 1.0364x over previous
#include <cuda_runtime.h>
#include <math.h>
#include <stdint.h>

#define NMAX 20000
#define EMAX 200000

// ---------------- scratch (static __device__; no cudaMalloc) ----------------
__device__ float g_pre[NMAX * 512];
__device__ float g_selfx[NMAX * 512];
__device__ float g_acc[NMAX * 512];
__device__ float g_xg[NMAX * 512];
__device__ float g_z[NMAX * 256];
__device__ float g_h[NMAX * 256];
__device__ float g_g[NMAX * 256];
__device__ float g_adst[NMAX * 32];
__device__ float g_ws1ab[128 * 32];
__device__ float g_hf[EMAX * 32];
__device__ float g_hs[EMAX * 32];

// ---------------- helpers ----------------------------------------------------
__device__ __forceinline__ float sspf(float v) {
    float sp = (v > 0.f) ? (v + log1pf(expf(-v))) : log1pf(expf(v));
    return sp - 0.693147180559945309f;
}
__device__ __forceinline__ float siluf(float v) {
    return v / (1.f + expf(-v));
}
__device__ __forceinline__ void red_add_v4(float* addr, float a, float b, float c, float d) {
    asm volatile("red.global.add.v4.f32 [%0], {%1,%2,%3,%4};"
                 :: "l"(addr), "f"(a), "f"(b), "f"(c), "f"(d) : "memory");
}
__device__ __forceinline__ uint32_t f2tf32(float f) {
    uint32_t u;
    asm("cvt.rna.tf32.f32 %0, %1;" : "=r"(u) : "f"(f));
    return u;
}
__device__ __forceinline__ void mma_tf32(float c[4], const uint32_t a[4],
                                         uint32_t b0, uint32_t b1) {
    asm volatile(
        "mma.sync.aligned.m16n8k8.row.col.f32.tf32.tf32.f32 "
        "{%0,%1,%2,%3}, {%4,%5,%6,%7}, {%8,%9}, {%0,%1,%2,%3};"
        : "+f"(c[0]), "+f"(c[1]), "+f"(c[2]), "+f"(c[3])
        : "r"(a[0]), "r"(a[1]), "r"(a[2]), "r"(a[3]), "r"(b0), "r"(b1));
}

// ---------------- ws1ab = W_s1[0:128] + W_s1[128:256] -----------------------
__global__ void k_prep(const float* __restrict__ W_s1, float* __restrict__ ws1ab) {
    int i = blockIdx.x * blockDim.x + threadIdx.x;
    if (i < 128 * 32) ws1ab[i] = W_s1[i] + W_s1[128 * 32 + i];
}

// ---------------- irrep_linear via tf32 mma (validated R8) -------------------
#define XSS 516
#define WSS 132
#define SM_IRREP_MMA ((32 * XSS + 2 * 32 * WSS) * 4)
__global__ void __launch_bounds__(256, 2) k_irrep(
    const float* __restrict__ X, const float* __restrict__ W0,
    const float* __restrict__ b0, const float* __restrict__ W1,
    float* __restrict__ Y, float* __restrict__ Y2,
    const float* __restrict__ resid, int nRows)
{
    extern __shared__ float smf[];
    float* Xs = smf;                                  // 32*516
    uint32_t* sW0 = (uint32_t*)(Xs + 32 * XSS);       // 32*132
    uint32_t* sW1 = sW0 + 32 * WSS;                   // 32*132
    const int tid = threadIdx.x;
    const int row0 = blockIdx.x * 32;
    const int warp = tid >> 5, lane = tid & 31;
    const int g = lane >> 2, t4 = lane & 3;
    const int kind = warp >> 1;
    const int nb = (warp & 1) * 16;

    for (int i = tid; i < 32 * 512; i += 256) {
        int r = i >> 9, c = i & 511;
        int gr = row0 + r;
        Xs[r * XSS + c] = (gr < nRows) ? X[(size_t)gr * 512 + c] : 0.f;
    }

    float acc[16][4];
#pragma unroll
    for (int i = 0; i < 16; i++)
#pragma unroll
        for (int j = 0; j < 4; j++) acc[i][j] = 0.f;

    for (int kc = 0; kc < 4; kc++) {
        __syncthreads();
        for (int i = tid; i < 32 * 128; i += 256) {
            int k = i >> 7, v = i & 127;
            sW0[k * WSS + v] = f2tf32(W0[(size_t)(kc * 32 + k) * 128 + v]);
            sW1[k * WSS + v] = f2tf32(W1[(size_t)(kc * 32 + k) * 128 + v]);
        }
        __syncthreads();
        const uint32_t* sB = (kind == 0) ? sW0 : sW1;
#pragma unroll
        for (int k8 = 0; k8 < 4; k8++) {
            const int kg = kc * 32 + k8 * 8;
            uint32_t a[4];
            if (kind == 0) {
                a[0] = f2tf32(Xs[(nb + g) * XSS + kg + t4]);
                a[1] = f2tf32(Xs[(nb + g + 8) * XSS + kg + t4]);
                a[2] = f2tf32(Xs[(nb + g) * XSS + kg + t4 + 4]);
                a[3] = f2tf32(Xs[(nb + g + 8) * XSS + kg + t4 + 4]);
            } else {
                const int c = kind - 1;
                a[0] = f2tf32(Xs[(nb + g) * XSS + 128 + (kg + t4) * 3 + c]);
                a[1] = f2tf32(Xs[(nb + g + 8) * XSS + 128 + (kg + t4) * 3 + c]);
                a[2] = f2tf32(Xs[(nb + g) * XSS + 128 + (kg + t4 + 4) * 3 + c]);
                a[3] = f2tf32(Xs[(nb + g + 8) * XSS + 128 + (kg + t4 + 4) * 3 + c]);
            }
#pragma unroll
            for (int nt = 0; nt < 16; nt++) {
                uint32_t br0 = sB[(k8 * 8 + t4) * WSS + nt * 8 + g];
                uint32_t br1 = sB[(k8 * 8 + t4 + 4) * WSS + nt * 8 + g];
                mma_tf32(acc[nt], a, br0, br1);
            }
        }
    }
    __syncthreads();
#pragma unroll
    for (int nt = 0; nt < 16; nt++) {
        const int c0 = nt * 8 + 2 * t4;
        const int n0 = nb + g, n1 = nb + g + 8;
        if (kind == 0) {
            Xs[n0 * XSS + c0]     = acc[nt][0];
            Xs[n0 * XSS + c0 + 1] = acc[nt][1];
            Xs[n1 * XSS + c0]     = acc[nt][2];
            Xs[n1 * XSS + c0 + 1] = acc[nt][3];
        } else {
            const int cc = kind - 1;
            Xs[n0 * XSS + 128 + c0 * 3 + cc]       = acc[nt][0];
            Xs[n0 * XSS + 128 + (c0 + 1) * 3 + cc] = acc[nt][1];
            Xs[n1 * XSS + 128 + c0 * 3 + cc]       = acc[nt][2];
            Xs[n1 * XSS + 128 + (c0 + 1) * 3 + cc] = acc[nt][3];
        }
    }
    __syncthreads();
    for (int i = tid; i < 32 * 128; i += 256) {
        int r = i >> 7, c = (i & 127) * 4;
        int n = row0 + r;
        if (n >= nRows) continue;
        size_t base = (size_t)n * 512 + c;
        float4 v = *reinterpret_cast<float4*>(&Xs[r * XSS + c]);
        if (c < 128) {
            float4 bb = *reinterpret_cast<const float4*>(&b0[c]);
            v.x += bb.x; v.y += bb.y; v.z += bb.z; v.w += bb.w;
        }
        if (resid) {
            float4 rr = *reinterpret_cast<const float4*>(&resid[base]);
            v.x += rr.x; v.y += rr.y; v.z += rr.z; v.w += rr.w;
        }
        *reinterpret_cast<float4*>(&Y[base]) = v;
        if (Y2) *reinterpret_cast<float4*>(&Y2[base]) = v;
    }
}

// ---------------- a_dst = p0 @ ws1ab ----------------------------------------
__global__ void __launch_bounds__(256) k_adst(
    const float* __restrict__ pre, const float* __restrict__ ws1ab,
    float* __restrict__ adst, int nRows)
{
    __shared__ float p0s[8 * 128];
    __shared__ float ws[128 * 32];
    const int tid = threadIdx.x;
    const int row0 = blockIdx.x * 8;
    for (int i = tid; i < 128 * 32; i += 256) ws[i] = ws1ab[i];
    for (int i = tid; i < 8 * 128; i += 256) {
        int r = i >> 7, c = i & 127;
        int gr = row0 + r;
        p0s[i] = (gr < nRows) ? pre[(size_t)gr * 512 + c] : 0.f;
    }
    __syncthreads();
    const int h = tid & 31, nl = tid >> 5;
    float acc = 0.f;
#pragma unroll 8
    for (int u = 0; u < 128; u++) acc += p0s[nl * 128 + u] * ws[u * 32 + h];
    int n = row0 + nl;
    if (n < nRows) adst[(size_t)n * 32 + h] = acc;
}

// ---------------- z = [x0, sqrt(mean_c x1^2)] --------------------------------
__global__ void k_znorm(const float* __restrict__ x, float* __restrict__ z, int nRows) {
    int t = blockIdx.x * blockDim.x + threadIdx.x;
    if (t >= nRows * 128) return;
    int n = t >> 7, u = t & 127;
    size_t b5 = (size_t)n * 512, b2 = (size_t)n * 256;
    z[b2 + u] = x[b5 + u];
    float a = x[b5 + 128 + u * 3 + 0];
    float b = x[b5 + 128 + u * 3 + 1];
    float c = x[b5 + 128 + u * 3 + 2];
    z[b2 + 128 + u] = sqrtf((a * a + b * b + c * c) * (1.f / 3.f));
}

// ---------------- dense 256x256 GEMM (k-quad inner loop, R12) ----------------
__global__ void __launch_bounds__(256, 3) k_gemm256(
    const float* __restrict__ X, const float* __restrict__ W,
    const float* __restrict__ b, float* __restrict__ Y, int nRows, int act)
{
    extern __shared__ float sm[];
    float* Xs = sm;             // 32*256
    float* Ws = sm + 32 * 256;  // 32*256
    const int tid = threadIdx.x;
    const int row0 = blockIdx.x * 32;
    for (int i = tid; i < 32 * 256; i += 256) {
        int r = i >> 8, c = i & 255;
        int gr = row0 + r;
        Xs[i] = (gr < nRows) ? X[(size_t)gr * 256 + c] : 0.f;
    }
    const int vg = tid & 63;
    const int ng = tid >> 6;
    float acc[8][4] = {};
    for (int kt = 0; kt < 8; kt++) {
        __syncthreads();
        for (int i = tid; i < 32 * 256; i += 256) {
            int r = i >> 8, c = i & 255;
            Ws[i] = W[(size_t)(kt * 32 + r) * 256 + c];
        }
        __syncthreads();
#pragma unroll
        for (int u4 = 0; u4 < 8; u4++) {
            float4 w0 = *reinterpret_cast<float4*>(&Ws[(u4 * 4 + 0) * 256 + vg * 4]);
            float4 w1 = *reinterpret_cast<float4*>(&Ws[(u4 * 4 + 1) * 256 + vg * 4]);
            float4 w2 = *reinterpret_cast<float4*>(&Ws[(u4 * 4 + 2) * 256 + vg * 4]);
            float4 w3 = *reinterpret_cast<float4*>(&Ws[(u4 * 4 + 3) * 256 + vg * 4]);
#pragma unroll
            for (int ni = 0; ni < 8; ni++) {
                float4 xv = *reinterpret_cast<float4*>(
                    &Xs[(ng * 8 + ni) * 256 + kt * 32 + u4 * 4]);
                acc[ni][0] += xv.x * w0.x + xv.y * w1.x + xv.z * w2.x + xv.w * w3.x;
                acc[ni][1] += xv.x * w0.y + xv.y * w1.y + xv.z * w2.y + xv.w * w3.y;
                acc[ni][2] += xv.x * w0.z + xv.y * w1.z + xv.z * w2.z + xv.w * w3.z;
                acc[ni][3] += xv.x * w0.w + xv.y * w1.w + xv.z * w2.w + xv.w * w3.w;
            }
        }
    }
    float4 bb = *reinterpret_cast<const float4*>(&b[vg * 4]);
    float bv[4] = {bb.x, bb.y, bb.z, bb.w};
#pragma unroll
    for (int ni = 0; ni < 8; ni++) {
        int n = row0 + ng * 8 + ni;
        if (n >= nRows) continue;
        float4 o; float* op = (float*)&o;
#pragma unroll
        for (int vi = 0; vi < 4; vi++) {
            float v = acc[ni][vi] + bv[vi];
            op[vi] = act ? siluf(v) : v;
        }
        *reinterpret_cast<float4*>(&Y[(size_t)n * 256 + vg * 4]) = o;
    }
}

// ---------------- xg = merge(g[:, :128], x1 * g[:, 128:, None]) --------------
__global__ void k_xg(const float* __restrict__ x, const float* __restrict__ g,
                     float* __restrict__ xg, int nRows) {
    int t = blockIdx.x * blockDim.x + threadIdx.x;
    if (t >= nRows * 128) return;
    int n = t >> 7, u = t & 127;
    size_t b5 = (size_t)n * 512, b2 = (size_t)n * 256;
    xg[b5 + u] = g[b2 + u];
    float gu = g[b2 + 128 + u];
    xg[b5 + 128 + u * 3 + 0] = x[b5 + 128 + u * 3 + 0] * gu;
    xg[b5 + 128 + u * 3 + 1] = x[b5 + 128 + u * 3 + 1] * gu;
    xg[b5 + 128 + u * 3 + 2] = x[b5 + 128 + u * 3 + 2] * gu;
}

// ---------------- k_h: R12 64-edge SIMT version (152 us proven) --------------
#define IPS 132
#define ATS 36
#define KH_SMEM_BYTES ((64 * IPS + 64 * ATS + 128 * 33 + 32 * 33) * 4 + 2 * 64 * 4)
__global__ void __launch_bounds__(256) k_h(
    const float* __restrict__ pre, const float* __restrict__ adst,
    const float* __restrict__ edge_attr, const int* __restrict__ edge_index,
    const float* __restrict__ W_s1, const float* __restrict__ W_f1,
    float* __restrict__ hf_out, float* __restrict__ hs_out, int E)
{
    extern __shared__ float smf[];
    float* sIp  = smf;
    float* sAt  = sIp + 64 * IPS;
    float* sWs  = sAt + 64 * ATS;
    float* sWf  = sWs + 128 * 33;
    int*   sDst = (int*)(sWf + 32 * 33);
    int*   sSrc = sDst + 64;
    const int tid = threadIdx.x;
    const int warp = tid >> 5, lane = tid & 31;
    const int e0 = blockIdx.x * 64;
    const float inv3 = 1.f / 3.f;

    if (tid < 64) {
        int e = e0 + tid;
        sDst[tid] = (e < E) ? edge_index[e] : 0;
        sSrc[tid] = (e < E) ? edge_index[E + e] : 0;
    }
    for (int i = tid; i < 128 * 32; i += 256) {
        int u = i >> 5, c = i & 31;
        sWs[u * 33 + c] = W_s1[256 * 32 + i];
    }
    for (int i = tid; i < 32 * 32; i += 256) {
        int u = i >> 5, c = i & 31;
        sWf[u * 33 + c] = W_f1[i];
    }
    __syncthreads();

#pragma unroll
    for (int s = 0; s < 8; s++) {
        const int el = warp * 8 + s;
        const int e  = e0 + el;
        const int ec = (e < E) ? e : 0;
        const int dst = sDst[el];
        const int src = sSrc[el];
        const float* pd = pre + (size_t)dst * 512 + 128 + 12 * lane;
        const float* ps = pre + (size_t)src * 512 + 128 + 12 * lane;
        float4 d0 = *(const float4*)(pd);
        float4 d1 = *(const float4*)(pd + 4);
        float4 d2 = *(const float4*)(pd + 8);
        float4 s0 = *(const float4*)(ps);
        float4 s1 = *(const float4*)(ps + 4);
        float4 s2 = *(const float4*)(ps + 8);
        float at = edge_attr[(size_t)ec * 32 + lane];
        float4 ipv;
        ipv.x = (d0.x * s0.x + d0.y * s0.y + d0.z * s0.z) * inv3;
        ipv.y = (d0.w * s0.w + d1.x * s1.x + d1.y * s1.y) * inv3;
        ipv.z = (d1.z * s1.z + d1.w * s1.w + d2.x * s2.x) * inv3;
        ipv.w = (d2.y * s2.y + d2.z * s2.z + d2.w * s2.w) * inv3;
        *(float4*)(sIp + el * IPS + 4 * lane) = ipv;
        sAt[el * ATS + lane] = at;
    }
    __syncthreads();

    const int cg = tid & 15, eg = tid >> 4;
    const int c0 = 2 * cg, c1 = c0 + 1;
    const int elb = eg * 4;
    float as0[4], as1[4];
#pragma unroll
    for (int i = 0; i < 4; i++) {
        int dst = sDst[elb + i];
        as0[i] = adst[(size_t)dst * 32 + c0];
        as1[i] = adst[(size_t)dst * 32 + c1];
    }
#pragma unroll 4
    for (int u4 = 0; u4 < 32; u4++) {
        float4 ip0 = *(const float4*)(sIp + (elb + 0) * IPS + u4 * 4);
        float4 ip1 = *(const float4*)(sIp + (elb + 1) * IPS + u4 * 4);
        float4 ip2 = *(const float4*)(sIp + (elb + 2) * IPS + u4 * 4);
        float4 ip3 = *(const float4*)(sIp + (elb + 3) * IPS + u4 * 4);
#pragma unroll
        for (int j = 0; j < 4; j++) {
            int u = u4 * 4 + j;
            float w0 = sWs[u * 33 + c0];
            float w1 = sWs[u * 33 + c1];
            float v0 = (&ip0.x)[j], v1 = (&ip1.x)[j], v2 = (&ip2.x)[j], v3 = (&ip3.x)[j];
            as0[0] += v0 * w0; as1[0] += v0 * w1;
            as0[1] += v1 * w0; as1[1] += v1 * w1;
            as0[2] += v2 * w0; as1[2] += v2 * w1;
            as0[3] += v3 * w0; as1[3] += v3 * w1;
        }
    }
    float af0[4] = {}, af1[4] = {};
#pragma unroll
    for (int u4 = 0; u4 < 8; u4++) {
        float4 a0 = *(const float4*)(sAt + (elb + 0) * ATS + u4 * 4);
        float4 a1 = *(const float4*)(sAt + (elb + 1) * ATS + u4 * 4);
        float4 a2 = *(const float4*)(sAt + (elb + 2) * ATS + u4 * 4);
        float4 a3 = *(const float4*)(sAt + (elb + 3) * ATS + u4 * 4);
#pragma unroll
        for (int j = 0; j < 4; j++) {
            int u = u4 * 4 + j;
            float w0 = sWf[u * 33 + c0];
            float w1 = sWf[u * 33 + c1];
            float v0 = (&a0.x)[j], v1 = (&a1.x)[j], v2 = (&a2.x)[j], v3 = (&a3.x)[j];
            af0[0] += v0 * w0; af1[0] += v0 * w1;
            af0[1] += v1 * w0; af1[1] += v1 * w1;
            af0[2] += v2 * w0; af1[2] += v2 * w1;
            af0[3] += v3 * w0; af1[3] += v3 * w1;
        }
    }
#pragma unroll
    for (int i = 0; i < 4; i++) {
        int e = e0 + elb + i;
        if (e >= E) continue;
        float2 vs; vs.x = sspf(as0[i]); vs.y = sspf(as1[i]);
        float2 vf; vf.x = sspf(af0[i]); vf.y = sspf(af1[i]);
        *reinterpret_cast<float2*>(&hs_out[(size_t)e * 32 + c0]) = vs;
        *reinterpret_cast<float2*>(&hf_out[(size_t)e * 32 + c0]) = vf;
    }
}

// ---------------- k_ws: fused w-GEMM + scatter, 64 edges / 512 thr -----------
// 1 block/SM (186.9 KB smem), 16 warps: same residency as R10's 2x8, but
// weight staging traffic halves (B tiles amortized over 64 edges).
#define FAS 36
#define FBS 136
#define FWS 520
#define SM_WS ((2 * 64 * FAS + 2 * 32 * FBS + 64 * FWS) * 4 + 2 * 64 * 4)
__global__ void __launch_bounds__(512, 1) k_ws(
    const float* __restrict__ hf, const float* __restrict__ hs,
    const float* __restrict__ Wf2, const float* __restrict__ Ws2,
    const float* __restrict__ selfx, const float* __restrict__ edge_sh,
    const int* __restrict__ edge_index, float* __restrict__ acc_out, int E)
{
    extern __shared__ uint32_t smu[];
    uint32_t* sAf = smu;                      // 64*36
    uint32_t* sAs = sAf + 64 * FAS;           // 64*36
    uint32_t* sBf = sAs + 64 * FAS;           // 32*136
    uint32_t* sBs = sBf + 32 * FBS;           // 32*136
    float*    sW  = (float*)(sBs + 32 * FBS); // 64*520
    int*      sDst = (int*)(sW + 64 * FWS);   // 64
    int*      sSrc = sDst + 64;               // 64
    const int tid = threadIdx.x;
    const int e0 = blockIdx.x * 64;
    const int warp = tid >> 5, lane = tid & 31;
    const int g = lane >> 2, t4 = lane & 3;
    const int mt = warp >> 2;                 // 0..3 -> rows mt*16..+15
    const int ch = warp & 3;                  // col quarter within section
    const int m0 = mt * 16;

    if (tid < 64) {
        int e = e0 + tid;
        sDst[tid] = (e < E) ? edge_index[e] : 0;
        sSrc[tid] = (e < E) ? edge_index[E + e] : 0;
    }
    for (int i = tid; i < 64 * 32; i += 512) {
        int r = i >> 5, c = i & 31;
        int e = e0 + r;
        float vf = (e < E) ? hf[(size_t)e * 32 + c] : 0.f;
        float vs = (e < E) ? hs[(size_t)e * 32 + c] : 0.f;
        sAf[r * FAS + c] = f2tf32(vf);
        sAs[r * FAS + c] = f2tf32(vs);
    }
    __syncthreads();

    uint32_t af[4][4], as_[4][4];
#pragma unroll
    for (int ks = 0; ks < 4; ks++) {
        const int k = ks * 8;
        af[ks][0] = sAf[(m0 + g) * FAS + k + t4];
        af[ks][1] = sAf[(m0 + g + 8) * FAS + k + t4];
        af[ks][2] = sAf[(m0 + g) * FAS + k + t4 + 4];
        af[ks][3] = sAf[(m0 + g + 8) * FAS + k + t4 + 4];
        as_[ks][0] = sAs[(m0 + g) * FAS + k + t4];
        as_[ks][1] = sAs[(m0 + g + 8) * FAS + k + t4];
        as_[ks][2] = sAs[(m0 + g) * FAS + k + t4 + 4];
        as_[ks][3] = sAs[(m0 + g + 8) * FAS + k + t4 + 4];
    }

    for (int sec = 0; sec < 4; sec++) {
        __syncthreads();
        for (int i = tid; i < 32 * 128; i += 512) {
            int k = i >> 7, c = i & 127;
            sBf[k * FBS + c] = f2tf32(Wf2[(size_t)k * 512 + sec * 128 + c]);
            sBs[k * FBS + c] = f2tf32(Ws2[(size_t)k * 512 + sec * 128 + c]);
        }
        __syncthreads();
#pragma unroll
        for (int nt = 0; nt < 4; nt++) {
            float cf[4] = {0.f, 0.f, 0.f, 0.f};
            float cs[4] = {0.f, 0.f, 0.f, 0.f};
            const int nb = ch * 32 + nt * 8 + g;
#pragma unroll
            for (int ks = 0; ks < 4; ks++) {
                const int k = ks * 8;
                uint32_t b0 = sBf[(k + t4) * FBS + nb];
                uint32_t b1 = sBf[(k + t4 + 4) * FBS + nb];
                mma_tf32(cf, af[ks], b0, b1);
                b0 = sBs[(k + t4) * FBS + nb];
                b1 = sBs[(k + t4 + 4) * FBS + nb];
                mma_tf32(cs, as_[ks], b0, b1);
            }
            const int col = sec * 128 + ch * 32 + nt * 8 + 2 * t4;
            sW[(m0 + g) * FWS + col]     = cf[0] * cs[0];
            sW[(m0 + g) * FWS + col + 1] = cf[1] * cs[1];
            sW[(m0 + g + 8) * FWS + col]     = cf[2] * cs[2];
            sW[(m0 + g + 8) * FWS + col + 1] = cf[3] * cs[3];
        }
    }
    __syncthreads();

    const float invs3 = 0.57735026918962576f;
#pragma unroll
    for (int j = 0; j < 4; j++) {
        const int el = warp * 4 + j;
        const int e = e0 + el;
        if (e >= E) continue;
        const int dst = sDst[el];
        const int src = sSrc[el];
        const float* we = sW + el * FWS;
        float4 wq0 = *(const float4*)(we + 0   + 4 * lane);
        float4 wq1 = *(const float4*)(we + 128 + 4 * lane);
        float4 wq2 = *(const float4*)(we + 256 + 4 * lane);
        float4 wq3 = *(const float4*)(we + 384 + 4 * lane);
        float w1[4] = {wq0.x, wq0.y, wq0.z, wq0.w};
        float w2[4] = {wq1.x, wq1.y, wq1.z, wq1.w};
        float w3[4] = {wq2.x, wq2.y, wq2.z, wq2.w};
        float w4[4] = {wq3.x, wq3.y, wq3.z, wq3.w};

        float4 shv = *(const float4*)(edge_sh + (size_t)e * 4);
        const float sh0 = shv.x, sh1x = shv.y, sh1y = shv.z, sh1z = shv.w;
        const float* xs = selfx + (size_t)src * 512;
        float* ao = acc_out + (size_t)dst * 512;
        float4 x0v = *(const float4*)(xs + 4 * lane);
        float4 xv0 = *(const float4*)(xs + 128 + 12 * lane);
        float4 xv1 = *(const float4*)(xs + 128 + 12 * lane + 4);
        float4 xv2 = *(const float4*)(xs + 128 + 12 * lane + 8);
        float x0e[4] = {x0v.x, x0v.y, x0v.z, x0v.w};
        float xa[4] = {xv0.x, xv0.w, xv1.z, xv2.y};
        float xb[4] = {xv0.y, xv1.x, xv1.w, xv2.z};
        float xc[4] = {xv0.z, xv1.y, xv2.x, xv2.w};
        float o0[4], oa[4], ob[4], oc[4];
#pragma unroll
        for (int i = 0; i < 4; i++) {
            o0[i] = w1[i] * x0e[i] * sh0
                  + w4[i] * (xa[i] * sh1x + xb[i] * sh1y + xc[i] * sh1z) * invs3;
            oa[i] = w2[i] * x0e[i] * sh1x + w3[i] * xa[i] * sh0;
            ob[i] = w2[i] * x0e[i] * sh1y + w3[i] * xb[i] * sh0;
            oc[i] = w2[i] * x0e[i] * sh1z + w3[i] * xc[i] * sh0;
        }
        red_add_v4(ao + 4 * lane, o0[0], o0[1], o0[2], o0[3]);
        red_add_v4(ao + 128 + 12 * lane,     oa[0], ob[0], oc[0], oa[1]);
        red_add_v4(ao + 128 + 12 * lane + 4, ob[1], oc[1], oa[2], ob[2]);
        red_add_v4(ao + 128 + 12 * lane + 8, oc[2], oa[3], ob[3], oc[3]);
    }
}

// ---------------- host ------------------------------------------------------
extern "C" void kernel_launch(void* const* d_in, const int* in_sizes, int n_in,
                              void* d_out, int out_size) {
    const float* x         = (const float*)d_in[0];
    const float* edge_sh   = (const float*)d_in[1];
    const float* edge_attr = (const float*)d_in[2];
    const int*   edge_idx  = (const int*)  d_in[3];
    const float* W_pre0 = (const float*)d_in[4];
    const float* b_pre0 = (const float*)d_in[5];
    const float* W_pre1 = (const float*)d_in[6];
    const float* W_nd0  = (const float*)d_in[7];
    const float* b_nd0  = (const float*)d_in[8];
    const float* W_nd1  = (const float*)d_in[9];
    const float* W_g1   = (const float*)d_in[10];
    const float* b_g1   = (const float*)d_in[11];
    const float* W_g2   = (const float*)d_in[12];
    const float* b_g2   = (const float*)d_in[13];
    const float* W_f1   = (const float*)d_in[14];
    const float* W_f2   = (const float*)d_in[15];
    const float* W_s1   = (const float*)d_in[16];
    const float* W_s2   = (const float*)d_in[17];
    const float* W_o0   = (const float*)d_in[18];
    const float* b_o0   = (const float*)d_in[19];
    const float* W_o1   = (const float*)d_in[20];
    float* out = (float*)d_out;

    const int N = in_sizes[0] / 512;
    const int E = in_sizes[3] / 2;

    float *pre, *selfx, *acc, *xg, *z, *h, *g, *adst, *ws1ab, *hf, *hs;
    cudaGetSymbolAddress((void**)&pre,   g_pre);
    cudaGetSymbolAddress((void**)&selfx, g_selfx);
    cudaGetSymbolAddress((void**)&acc,   g_acc);
    cudaGetSymbolAddress((void**)&xg,    g_xg);
    cudaGetSymbolAddress((void**)&z,     g_z);
    cudaGetSymbolAddress((void**)&h,     g_h);
    cudaGetSymbolAddress((void**)&g,     g_g);
    cudaGetSymbolAddress((void**)&adst,  g_adst);
    cudaGetSymbolAddress((void**)&ws1ab, g_ws1ab);
    cudaGetSymbolAddress((void**)&hf,    g_hf);
    cudaGetSymbolAddress((void**)&hs,    g_hs);

    const int SM_GEMM = (2 * 32 * 256) * 4;                    // 65536
    const int SM_H    = KH_SMEM_BYTES;                         // 64640
    cudaFuncSetAttribute(k_irrep,   cudaFuncAttributeMaxDynamicSharedMemorySize, SM_IRREP_MMA);
    cudaFuncSetAttribute(k_gemm256, cudaFuncAttributeMaxDynamicSharedMemorySize, SM_GEMM);
    cudaFuncSetAttribute(k_h,       cudaFuncAttributeMaxDynamicSharedMemorySize, SM_H);
    cudaFuncSetAttribute(k_ws,      cudaFuncAttributeMaxDynamicSharedMemorySize, SM_WS);

    const int gIr = (N + 31) / 32;
    const int gEl = (N * 128 + 255) / 256;

    // 1) pre = irrep_linear(x, W_pre)
    k_irrep<<<gIr, 256, SM_IRREP_MMA>>>(x, W_pre0, b_pre0, W_pre1, pre, nullptr, nullptr, N);
    // 2) ws1ab, a_dst, edge hidden activations
    k_prep<<<16, 256>>>(W_s1, ws1ab);
    k_adst<<<(N + 7) / 8, 256>>>(pre, ws1ab, adst, N);
    k_h<<<(E + 63) / 64, 256, SM_H>>>(pre, adst, edge_attr, edge_idx, W_s1, W_f1, hf, hs, E);
    // 3) gate path (SIMT, separate elementwise — R12 proven)
    k_znorm<<<gEl, 256>>>(x, z, N);
    k_gemm256<<<gIr, 256, SM_GEMM>>>(z, W_g1, b_g1, h, N, 1);
    k_gemm256<<<gIr, 256, SM_GEMM>>>(h, W_g2, b_g2, g, N, 0);
    k_xg<<<gEl, 256>>>(x, g, xg, N);
    // 4) selfx = irrep_linear(xg, W_nd); dual-write accumulator init
    k_irrep<<<gIr, 256, SM_IRREP_MMA>>>(xg, W_nd0, b_nd0, W_nd1, selfx, acc, nullptr, N);
    // 5) fused w-GEMM + edge features + segment sum into acc (64-edge blocks)
    k_ws<<<(E + 63) / 64, 512, SM_WS>>>(hf, hs, W_f2, W_s2, selfx, edge_sh,
                                        edge_idx, acc, E);
    // 6) out = irrep_linear(acc, W_o) + x
    k_irrep<<<gIr, 256, SM_IRREP_MMA>>>(acc, W_o0, b_o0, W_o1, out, nullptr, x, N);
}

// round 17
// speedup vs baseline: 1.1072x; 1.0683x over previous
#include <cuda_runtime.h>
#include <math.h>
#include <stdint.h>

#define NMAX 20000
#define EMAX 200000

// ---------------- scratch (static __device__; no cudaMalloc) ----------------
__device__ float g_pre[NMAX * 512];
__device__ float g_selfx[NMAX * 512];
__device__ float g_acc[NMAX * 512];
__device__ float g_xg[NMAX * 512];
__device__ float g_z[NMAX * 256];
__device__ float g_h[NMAX * 256];
__device__ float g_g[NMAX * 256];
__device__ float g_adst[NMAX * 32];
__device__ float g_ws1ab[128 * 32];
__device__ float g_hf[EMAX * 32];
__device__ float g_hs[EMAX * 32];

// ---------------- helpers ----------------------------------------------------
__device__ __forceinline__ float sspf(float v) {
    float sp = (v > 0.f) ? (v + log1pf(expf(-v))) : log1pf(expf(v));
    return sp - 0.693147180559945309f;
}
__device__ __forceinline__ float siluf(float v) {
    return v / (1.f + expf(-v));
}
__device__ __forceinline__ void red_add_v4(float* addr, float a, float b, float c, float d) {
    asm volatile("red.global.add.v4.f32 [%0], {%1,%2,%3,%4};"
                 :: "l"(addr), "f"(a), "f"(b), "f"(c), "f"(d) : "memory");
}
__device__ __forceinline__ uint32_t f2tf32(float f) {
    uint32_t u;
    asm("cvt.rna.tf32.f32 %0, %1;" : "=r"(u) : "f"(f));
    return u;
}
__device__ __forceinline__ void mma_tf32(float c[4], const uint32_t a[4],
                                         uint32_t b0, uint32_t b1) {
    asm volatile(
        "mma.sync.aligned.m16n8k8.row.col.f32.tf32.tf32.f32 "
        "{%0,%1,%2,%3}, {%4,%5,%6,%7}, {%8,%9}, {%0,%1,%2,%3};"
        : "+f"(c[0]), "+f"(c[1]), "+f"(c[2]), "+f"(c[3])
        : "r"(a[0]), "r"(a[1]), "r"(a[2]), "r"(a[3]), "r"(b0), "r"(b1));
}

// ---------------- ws1ab = W_s1[0:128] + W_s1[128:256] -----------------------
__global__ void k_prep(const float* __restrict__ W_s1, float* __restrict__ ws1ab) {
    int i = blockIdx.x * blockDim.x + threadIdx.x;
    if (i < 128 * 32) ws1ab[i] = W_s1[i] + W_s1[128 * 32 + i];
}

// ---------------- irrep_linear via tf32 mma (validated R8) -------------------
#define XSS 516
#define WSS 132
#define SM_IRREP_MMA ((32 * XSS + 2 * 32 * WSS) * 4)
__global__ void __launch_bounds__(256, 2) k_irrep(
    const float* __restrict__ X, const float* __restrict__ W0,
    const float* __restrict__ b0, const float* __restrict__ W1,
    float* __restrict__ Y, float* __restrict__ Y2,
    const float* __restrict__ resid, int nRows)
{
    extern __shared__ float smf[];
    float* Xs = smf;                                  // 32*516
    uint32_t* sW0 = (uint32_t*)(Xs + 32 * XSS);       // 32*132
    uint32_t* sW1 = sW0 + 32 * WSS;                   // 32*132
    const int tid = threadIdx.x;
    const int row0 = blockIdx.x * 32;
    const int warp = tid >> 5, lane = tid & 31;
    const int g = lane >> 2, t4 = lane & 3;
    const int kind = warp >> 1;
    const int nb = (warp & 1) * 16;

    for (int i = tid; i < 32 * 512; i += 256) {
        int r = i >> 9, c = i & 511;
        int gr = row0 + r;
        Xs[r * XSS + c] = (gr < nRows) ? X[(size_t)gr * 512 + c] : 0.f;
    }

    float acc[16][4];
#pragma unroll
    for (int i = 0; i < 16; i++)
#pragma unroll
        for (int j = 0; j < 4; j++) acc[i][j] = 0.f;

    for (int kc = 0; kc < 4; kc++) {
        __syncthreads();
        for (int i = tid; i < 32 * 128; i += 256) {
            int k = i >> 7, v = i & 127;
            sW0[k * WSS + v] = f2tf32(W0[(size_t)(kc * 32 + k) * 128 + v]);
            sW1[k * WSS + v] = f2tf32(W1[(size_t)(kc * 32 + k) * 128 + v]);
        }
        __syncthreads();
        const uint32_t* sB = (kind == 0) ? sW0 : sW1;
#pragma unroll
        for (int k8 = 0; k8 < 4; k8++) {
            const int kg = kc * 32 + k8 * 8;
            uint32_t a[4];
            if (kind == 0) {
                a[0] = f2tf32(Xs[(nb + g) * XSS + kg + t4]);
                a[1] = f2tf32(Xs[(nb + g + 8) * XSS + kg + t4]);
                a[2] = f2tf32(Xs[(nb + g) * XSS + kg + t4 + 4]);
                a[3] = f2tf32(Xs[(nb + g + 8) * XSS + kg + t4 + 4]);
            } else {
                const int c = kind - 1;
                a[0] = f2tf32(Xs[(nb + g) * XSS + 128 + (kg + t4) * 3 + c]);
                a[1] = f2tf32(Xs[(nb + g + 8) * XSS + 128 + (kg + t4) * 3 + c]);
                a[2] = f2tf32(Xs[(nb + g) * XSS + 128 + (kg + t4 + 4) * 3 + c]);
                a[3] = f2tf32(Xs[(nb + g + 8) * XSS + 128 + (kg + t4 + 4) * 3 + c]);
            }
#pragma unroll
            for (int nt = 0; nt < 16; nt++) {
                uint32_t br0 = sB[(k8 * 8 + t4) * WSS + nt * 8 + g];
                uint32_t br1 = sB[(k8 * 8 + t4 + 4) * WSS + nt * 8 + g];
                mma_tf32(acc[nt], a, br0, br1);
            }
        }
    }
    __syncthreads();
#pragma unroll
    for (int nt = 0; nt < 16; nt++) {
        const int c0 = nt * 8 + 2 * t4;
        const int n0 = nb + g, n1 = nb + g + 8;
        if (kind == 0) {
            Xs[n0 * XSS + c0]     = acc[nt][0];
            Xs[n0 * XSS + c0 + 1] = acc[nt][1];
            Xs[n1 * XSS + c0]     = acc[nt][2];
            Xs[n1 * XSS + c0 + 1] = acc[nt][3];
        } else {
            const int cc = kind - 1;
            Xs[n0 * XSS + 128 + c0 * 3 + cc]       = acc[nt][0];
            Xs[n0 * XSS + 128 + (c0 + 1) * 3 + cc] = acc[nt][1];
            Xs[n1 * XSS + 128 + c0 * 3 + cc]       = acc[nt][2];
            Xs[n1 * XSS + 128 + (c0 + 1) * 3 + cc] = acc[nt][3];
        }
    }
    __syncthreads();
    for (int i = tid; i < 32 * 128; i += 256) {
        int r = i >> 7, c = (i & 127) * 4;
        int n = row0 + r;
        if (n >= nRows) continue;
        size_t base = (size_t)n * 512 + c;
        float4 v = *reinterpret_cast<float4*>(&Xs[r * XSS + c]);
        if (c < 128) {
            float4 bb = *reinterpret_cast<const float4*>(&b0[c]);
            v.x += bb.x; v.y += bb.y; v.z += bb.z; v.w += bb.w;
        }
        if (resid) {
            float4 rr = *reinterpret_cast<const float4*>(&resid[base]);
            v.x += rr.x; v.y += rr.y; v.z += rr.z; v.w += rr.w;
        }
        *reinterpret_cast<float4*>(&Y[base]) = v;
        if (Y2) *reinterpret_cast<float4*>(&Y2[base]) = v;
    }
}

// ---------------- a_dst = p0 @ ws1ab ----------------------------------------
__global__ void __launch_bounds__(256) k_adst(
    const float* __restrict__ pre, const float* __restrict__ ws1ab,
    float* __restrict__ adst, int nRows)
{
    __shared__ float p0s[8 * 128];
    __shared__ float ws[128 * 32];
    const int tid = threadIdx.x;
    const int row0 = blockIdx.x * 8;
    for (int i = tid; i < 128 * 32; i += 256) ws[i] = ws1ab[i];
    for (int i = tid; i < 8 * 128; i += 256) {
        int r = i >> 7, c = i & 127;
        int gr = row0 + r;
        p0s[i] = (gr < nRows) ? pre[(size_t)gr * 512 + c] : 0.f;
    }
    __syncthreads();
    const int h = tid & 31, nl = tid >> 5;
    float acc = 0.f;
#pragma unroll 8
    for (int u = 0; u < 128; u++) acc += p0s[nl * 128 + u] * ws[u * 32 + h];
    int n = row0 + nl;
    if (n < nRows) adst[(size_t)n * 32 + h] = acc;
}

// ---------------- z = [x0, sqrt(mean_c x1^2)] --------------------------------
__global__ void k_znorm(const float* __restrict__ x, float* __restrict__ z, int nRows) {
    int t = blockIdx.x * blockDim.x + threadIdx.x;
    if (t >= nRows * 128) return;
    int n = t >> 7, u = t & 127;
    size_t b5 = (size_t)n * 512, b2 = (size_t)n * 256;
    z[b2 + u] = x[b5 + u];
    float a = x[b5 + 128 + u * 3 + 0];
    float b = x[b5 + 128 + u * 3 + 1];
    float c = x[b5 + 128 + u * 3 + 2];
    z[b2 + 128 + u] = sqrtf((a * a + b * b + c * c) * (1.f / 3.f));
}

// ---------------- dense 256x256 GEMM (k-quad inner loop, R12) ----------------
__global__ void __launch_bounds__(256, 3) k_gemm256(
    const float* __restrict__ X, const float* __restrict__ W,
    const float* __restrict__ b, float* __restrict__ Y, int nRows, int act)
{
    extern __shared__ float sm[];
    float* Xs = sm;             // 32*256
    float* Ws = sm + 32 * 256;  // 32*256
    const int tid = threadIdx.x;
    const int row0 = blockIdx.x * 32;
    for (int i = tid; i < 32 * 256; i += 256) {
        int r = i >> 8, c = i & 255;
        int gr = row0 + r;
        Xs[i] = (gr < nRows) ? X[(size_t)gr * 256 + c] : 0.f;
    }
    const int vg = tid & 63;
    const int ng = tid >> 6;
    float acc[8][4] = {};
    for (int kt = 0; kt < 8; kt++) {
        __syncthreads();
        for (int i = tid; i < 32 * 256; i += 256) {
            int r = i >> 8, c = i & 255;
            Ws[i] = W[(size_t)(kt * 32 + r) * 256 + c];
        }
        __syncthreads();
#pragma unroll
        for (int u4 = 0; u4 < 8; u4++) {
            float4 w0 = *reinterpret_cast<float4*>(&Ws[(u4 * 4 + 0) * 256 + vg * 4]);
            float4 w1 = *reinterpret_cast<float4*>(&Ws[(u4 * 4 + 1) * 256 + vg * 4]);
            float4 w2 = *reinterpret_cast<float4*>(&Ws[(u4 * 4 + 2) * 256 + vg * 4]);
            float4 w3 = *reinterpret_cast<float4*>(&Ws[(u4 * 4 + 3) * 256 + vg * 4]);
#pragma unroll
            for (int ni = 0; ni < 8; ni++) {
                float4 xv = *reinterpret_cast<float4*>(
                    &Xs[(ng * 8 + ni) * 256 + kt * 32 + u4 * 4]);
                acc[ni][0] += xv.x * w0.x + xv.y * w1.x + xv.z * w2.x + xv.w * w3.x;
                acc[ni][1] += xv.x * w0.y + xv.y * w1.y + xv.z * w2.y + xv.w * w3.y;
                acc[ni][2] += xv.x * w0.z + xv.y * w1.z + xv.z * w2.z + xv.w * w3.z;
                acc[ni][3] += xv.x * w0.w + xv.y * w1.w + xv.z * w2.w + xv.w * w3.w;
            }
        }
    }
    float4 bb = *reinterpret_cast<const float4*>(&b[vg * 4]);
    float bv[4] = {bb.x, bb.y, bb.z, bb.w};
#pragma unroll
    for (int ni = 0; ni < 8; ni++) {
        int n = row0 + ng * 8 + ni;
        if (n >= nRows) continue;
        float4 o; float* op = (float*)&o;
#pragma unroll
        for (int vi = 0; vi < 4; vi++) {
            float v = acc[ni][vi] + bv[vi];
            op[vi] = act ? siluf(v) : v;
        }
        *reinterpret_cast<float4*>(&Y[(size_t)n * 256 + vg * 4]) = o;
    }
}

// ---------------- xg = merge(g[:, :128], x1 * g[:, 128:, None]) --------------
__global__ void k_xg(const float* __restrict__ x, const float* __restrict__ g,
                     float* __restrict__ xg, int nRows) {
    int t = blockIdx.x * blockDim.x + threadIdx.x;
    if (t >= nRows * 128) return;
    int n = t >> 7, u = t & 127;
    size_t b5 = (size_t)n * 512, b2 = (size_t)n * 256;
    xg[b5 + u] = g[b2 + u];
    float gu = g[b2 + 128 + u];
    xg[b5 + 128 + u * 3 + 0] = x[b5 + 128 + u * 3 + 0] * gu;
    xg[b5 + 128 + u * 3 + 1] = x[b5 + 128 + u * 3 + 1] * gu;
    xg[b5 + 128 + u * 3 + 2] = x[b5 + 128 + u * 3 + 2] * gu;
}

// ---------------- k_h: R12 64-edge SIMT version (152 us proven) --------------
#define IPS 132
#define ATS 36
#define KH_SMEM_BYTES ((64 * IPS + 64 * ATS + 128 * 33 + 32 * 33) * 4 + 2 * 64 * 4)
__global__ void __launch_bounds__(256) k_h(
    const float* __restrict__ pre, const float* __restrict__ adst,
    const float* __restrict__ edge_attr, const int* __restrict__ edge_index,
    const float* __restrict__ W_s1, const float* __restrict__ W_f1,
    float* __restrict__ hf_out, float* __restrict__ hs_out, int E)
{
    extern __shared__ float smf[];
    float* sIp  = smf;
    float* sAt  = sIp + 64 * IPS;
    float* sWs  = sAt + 64 * ATS;
    float* sWf  = sWs + 128 * 33;
    int*   sDst = (int*)(sWf + 32 * 33);
    int*   sSrc = sDst + 64;
    const int tid = threadIdx.x;
    const int warp = tid >> 5, lane = tid & 31;
    const int e0 = blockIdx.x * 64;
    const float inv3 = 1.f / 3.f;

    if (tid < 64) {
        int e = e0 + tid;
        sDst[tid] = (e < E) ? edge_index[e] : 0;
        sSrc[tid] = (e < E) ? edge_index[E + e] : 0;
    }
    for (int i = tid; i < 128 * 32; i += 256) {
        int u = i >> 5, c = i & 31;
        sWs[u * 33 + c] = W_s1[256 * 32 + i];
    }
    for (int i = tid; i < 32 * 32; i += 256) {
        int u = i >> 5, c = i & 31;
        sWf[u * 33 + c] = W_f1[i];
    }
    __syncthreads();

#pragma unroll
    for (int s = 0; s < 8; s++) {
        const int el = warp * 8 + s;
        const int e  = e0 + el;
        const int ec = (e < E) ? e : 0;
        const int dst = sDst[el];
        const int src = sSrc[el];
        const float* pd = pre + (size_t)dst * 512 + 128 + 12 * lane;
        const float* ps = pre + (size_t)src * 512 + 128 + 12 * lane;
        float4 d0 = *(const float4*)(pd);
        float4 d1 = *(const float4*)(pd + 4);
        float4 d2 = *(const float4*)(pd + 8);
        float4 s0 = *(const float4*)(ps);
        float4 s1 = *(const float4*)(ps + 4);
        float4 s2 = *(const float4*)(ps + 8);
        float at = edge_attr[(size_t)ec * 32 + lane];
        float4 ipv;
        ipv.x = (d0.x * s0.x + d0.y * s0.y + d0.z * s0.z) * inv3;
        ipv.y = (d0.w * s0.w + d1.x * s1.x + d1.y * s1.y) * inv3;
        ipv.z = (d1.z * s1.z + d1.w * s1.w + d2.x * s2.x) * inv3;
        ipv.w = (d2.y * s2.y + d2.z * s2.z + d2.w * s2.w) * inv3;
        *(float4*)(sIp + el * IPS + 4 * lane) = ipv;
        sAt[el * ATS + lane] = at;
    }
    __syncthreads();

    const int cg = tid & 15, eg = tid >> 4;
    const int c0 = 2 * cg, c1 = c0 + 1;
    const int elb = eg * 4;
    float as0[4], as1[4];
#pragma unroll
    for (int i = 0; i < 4; i++) {
        int dst = sDst[elb + i];
        as0[i] = adst[(size_t)dst * 32 + c0];
        as1[i] = adst[(size_t)dst * 32 + c1];
    }
#pragma unroll 4
    for (int u4 = 0; u4 < 32; u4++) {
        float4 ip0 = *(const float4*)(sIp + (elb + 0) * IPS + u4 * 4);
        float4 ip1 = *(const float4*)(sIp + (elb + 1) * IPS + u4 * 4);
        float4 ip2 = *(const float4*)(sIp + (elb + 2) * IPS + u4 * 4);
        float4 ip3 = *(const float4*)(sIp + (elb + 3) * IPS + u4 * 4);
#pragma unroll
        for (int j = 0; j < 4; j++) {
            int u = u4 * 4 + j;
            float w0 = sWs[u * 33 + c0];
            float w1 = sWs[u * 33 + c1];
            float v0 = (&ip0.x)[j], v1 = (&ip1.x)[j], v2 = (&ip2.x)[j], v3 = (&ip3.x)[j];
            as0[0] += v0 * w0; as1[0] += v0 * w1;
            as0[1] += v1 * w0; as1[1] += v1 * w1;
            as0[2] += v2 * w0; as1[2] += v2 * w1;
            as0[3] += v3 * w0; as1[3] += v3 * w1;
        }
    }
    float af0[4] = {}, af1[4] = {};
#pragma unroll
    for (int u4 = 0; u4 < 8; u4++) {
        float4 a0 = *(const float4*)(sAt + (elb + 0) * ATS + u4 * 4);
        float4 a1 = *(const float4*)(sAt + (elb + 1) * ATS + u4 * 4);
        float4 a2 = *(const float4*)(sAt + (elb + 2) * ATS + u4 * 4);
        float4 a3 = *(const float4*)(sAt + (elb + 3) * ATS + u4 * 4);
#pragma unroll
        for (int j = 0; j < 4; j++) {
            int u = u4 * 4 + j;
            float w0 = sWf[u * 33 + c0];
            float w1 = sWf[u * 33 + c1];
            float v0 = (&a0.x)[j], v1 = (&a1.x)[j], v2 = (&a2.x)[j], v3 = (&a3.x)[j];
            af0[0] += v0 * w0; af1[0] += v0 * w1;
            af0[1] += v1 * w0; af1[1] += v1 * w1;
            af0[2] += v2 * w0; af1[2] += v2 * w1;
            af0[3] += v3 * w0; af1[3] += v3 * w1;
        }
    }
#pragma unroll
    for (int i = 0; i < 4; i++) {
        int e = e0 + elb + i;
        if (e >= E) continue;
        float2 vs; vs.x = sspf(as0[i]); vs.y = sspf(as1[i]);
        float2 vf; vf.x = sspf(af0[i]); vf.y = sspf(af1[i]);
        *reinterpret_cast<float2*>(&hs_out[(size_t)e * 32 + c0]) = vs;
        *reinterpret_cast<float2*>(&hf_out[(size_t)e * 32 + c0]) = vf;
    }
}

// ---------------- k_ws: fused w-GEMM + scatter, 64 edges / 512 thr (R15) -----
#define FAS 36
#define FBS 136
#define FWS 520
#define SM_WS ((2 * 64 * FAS + 2 * 32 * FBS + 64 * FWS) * 4 + 2 * 64 * 4)
__global__ void __launch_bounds__(512, 1) k_ws(
    const float* __restrict__ hf, const float* __restrict__ hs,
    const float* __restrict__ Wf2, const float* __restrict__ Ws2,
    const float* __restrict__ selfx, const float* __restrict__ edge_sh,
    const int* __restrict__ edge_index, float* __restrict__ acc_out, int E)
{
    extern __shared__ uint32_t smu[];
    uint32_t* sAf = smu;                      // 64*36
    uint32_t* sAs = sAf + 64 * FAS;           // 64*36
    uint32_t* sBf = sAs + 64 * FAS;           // 32*136
    uint32_t* sBs = sBf + 32 * FBS;           // 32*136
    float*    sW  = (float*)(sBs + 32 * FBS); // 64*520
    int*      sDst = (int*)(sW + 64 * FWS);   // 64
    int*      sSrc = sDst + 64;               // 64
    const int tid = threadIdx.x;
    const int e0 = blockIdx.x * 64;
    const int warp = tid >> 5, lane = tid & 31;
    const int g = lane >> 2, t4 = lane & 3;
    const int mt = warp >> 2;
    const int ch = warp & 3;
    const int m0 = mt * 16;

    if (tid < 64) {
        int e = e0 + tid;
        sDst[tid] = (e < E) ? edge_index[e] : 0;
        sSrc[tid] = (e < E) ? edge_index[E + e] : 0;
    }
    for (int i = tid; i < 64 * 32; i += 512) {
        int r = i >> 5, c = i & 31;
        int e = e0 + r;
        float vf = (e < E) ? hf[(size_t)e * 32 + c] : 0.f;
        float vs = (e < E) ? hs[(size_t)e * 32 + c] : 0.f;
        sAf[r * FAS + c] = f2tf32(vf);
        sAs[r * FAS + c] = f2tf32(vs);
    }
    __syncthreads();

    uint32_t af[4][4], as_[4][4];
#pragma unroll
    for (int ks = 0; ks < 4; ks++) {
        const int k = ks * 8;
        af[ks][0] = sAf[(m0 + g) * FAS + k + t4];
        af[ks][1] = sAf[(m0 + g + 8) * FAS + k + t4];
        af[ks][2] = sAf[(m0 + g) * FAS + k + t4 + 4];
        af[ks][3] = sAf[(m0 + g + 8) * FAS + k + t4 + 4];
        as_[ks][0] = sAs[(m0 + g) * FAS + k + t4];
        as_[ks][1] = sAs[(m0 + g + 8) * FAS + k + t4];
        as_[ks][2] = sAs[(m0 + g) * FAS + k + t4 + 4];
        as_[ks][3] = sAs[(m0 + g + 8) * FAS + k + t4 + 4];
    }

    for (int sec = 0; sec < 4; sec++) {
        __syncthreads();
        for (int i = tid; i < 32 * 128; i += 512) {
            int k = i >> 7, c = i & 127;
            sBf[k * FBS + c] = f2tf32(Wf2[(size_t)k * 512 + sec * 128 + c]);
            sBs[k * FBS + c] = f2tf32(Ws2[(size_t)k * 512 + sec * 128 + c]);
        }
        __syncthreads();
#pragma unroll
        for (int nt = 0; nt < 4; nt++) {
            float cf[4] = {0.f, 0.f, 0.f, 0.f};
            float cs[4] = {0.f, 0.f, 0.f, 0.f};
            const int nb = ch * 32 + nt * 8 + g;
#pragma unroll
            for (int ks = 0; ks < 4; ks++) {
                const int k = ks * 8;
                uint32_t b0 = sBf[(k + t4) * FBS + nb];
                uint32_t b1 = sBf[(k + t4 + 4) * FBS + nb];
                mma_tf32(cf, af[ks], b0, b1);
                b0 = sBs[(k + t4) * FBS + nb];
                b1 = sBs[(k + t4 + 4) * FBS + nb];
                mma_tf32(cs, as_[ks], b0, b1);
            }
            const int col = sec * 128 + ch * 32 + nt * 8 + 2 * t4;
            sW[(m0 + g) * FWS + col]     = cf[0] * cs[0];
            sW[(m0 + g) * FWS + col + 1] = cf[1] * cs[1];
            sW[(m0 + g + 8) * FWS + col]     = cf[2] * cs[2];
            sW[(m0 + g + 8) * FWS + col + 1] = cf[3] * cs[3];
        }
    }
    __syncthreads();

    const float invs3 = 0.57735026918962576f;
#pragma unroll
    for (int j = 0; j < 4; j++) {
        const int el = warp * 4 + j;
        const int e = e0 + el;
        if (e >= E) continue;
        const int dst = sDst[el];
        const int src = sSrc[el];
        const float* we = sW + el * FWS;
        float4 wq0 = *(const float4*)(we + 0   + 4 * lane);
        float4 wq1 = *(const float4*)(we + 128 + 4 * lane);
        float4 wq2 = *(const float4*)(we + 256 + 4 * lane);
        float4 wq3 = *(const float4*)(we + 384 + 4 * lane);
        float w1[4] = {wq0.x, wq0.y, wq0.z, wq0.w};
        float w2[4] = {wq1.x, wq1.y, wq1.z, wq1.w};
        float w3[4] = {wq2.x, wq2.y, wq2.z, wq2.w};
        float w4[4] = {wq3.x, wq3.y, wq3.z, wq3.w};

        float4 shv = *(const float4*)(edge_sh + (size_t)e * 4);
        const float sh0 = shv.x, sh1x = shv.y, sh1y = shv.z, sh1z = shv.w;
        const float* xs = selfx + (size_t)src * 512;
        float* ao = acc_out + (size_t)dst * 512;
        float4 x0v = *(const float4*)(xs + 4 * lane);
        float4 xv0 = *(const float4*)(xs + 128 + 12 * lane);
        float4 xv1 = *(const float4*)(xs + 128 + 12 * lane + 4);
        float4 xv2 = *(const float4*)(xs + 128 + 12 * lane + 8);
        float x0e[4] = {x0v.x, x0v.y, x0v.z, x0v.w};
        float xa[4] = {xv0.x, xv0.w, xv1.z, xv2.y};
        float xb[4] = {xv0.y, xv1.x, xv1.w, xv2.z};
        float xc[4] = {xv0.z, xv1.y, xv2.x, xv2.w};
        float o0[4], oa[4], ob[4], oc[4];
#pragma unroll
        for (int i = 0; i < 4; i++) {
            o0[i] = w1[i] * x0e[i] * sh0
                  + w4[i] * (xa[i] * sh1x + xb[i] * sh1y + xc[i] * sh1z) * invs3;
            oa[i] = w2[i] * x0e[i] * sh1x + w3[i] * xa[i] * sh0;
            ob[i] = w2[i] * x0e[i] * sh1y + w3[i] * xb[i] * sh0;
            oc[i] = w2[i] * x0e[i] * sh1z + w3[i] * xc[i] * sh0;
        }
        red_add_v4(ao + 4 * lane, o0[0], o0[1], o0[2], o0[3]);
        red_add_v4(ao + 128 + 12 * lane,     oa[0], ob[0], oc[0], oa[1]);
        red_add_v4(ao + 128 + 12 * lane + 4, ob[1], oc[1], oa[2], ob[2]);
        red_add_v4(ao + 128 + 12 * lane + 8, oc[2], oa[3], ob[3], oc[3]);
    }
}

// ---------------- host ------------------------------------------------------
extern "C" void kernel_launch(void* const* d_in, const int* in_sizes, int n_in,
                              void* d_out, int out_size) {
    const float* x         = (const float*)d_in[0];
    const float* edge_sh   = (const float*)d_in[1];
    const float* edge_attr = (const float*)d_in[2];
    const int*   edge_idx  = (const int*)  d_in[3];
    const float* W_pre0 = (const float*)d_in[4];
    const float* b_pre0 = (const float*)d_in[5];
    const float* W_pre1 = (const float*)d_in[6];
    const float* W_nd0  = (const float*)d_in[7];
    const float* b_nd0  = (const float*)d_in[8];
    const float* W_nd1  = (const float*)d_in[9];
    const float* W_g1   = (const float*)d_in[10];
    const float* b_g1   = (const float*)d_in[11];
    const float* W_g2   = (const float*)d_in[12];
    const float* b_g2   = (const float*)d_in[13];
    const float* W_f1   = (const float*)d_in[14];
    const float* W_f2   = (const float*)d_in[15];
    const float* W_s1   = (const float*)d_in[16];
    const float* W_s2   = (const float*)d_in[17];
    const float* W_o0   = (const float*)d_in[18];
    const float* b_o0   = (const float*)d_in[19];
    const float* W_o1   = (const float*)d_in[20];
    float* out = (float*)d_out;

    const int N = in_sizes[0] / 512;
    const int E = in_sizes[3] / 2;

    float *pre, *selfx, *acc, *xg, *z, *h, *g, *adst, *ws1ab, *hf, *hs;
    cudaGetSymbolAddress((void**)&pre,   g_pre);
    cudaGetSymbolAddress((void**)&selfx, g_selfx);
    cudaGetSymbolAddress((void**)&acc,   g_acc);
    cudaGetSymbolAddress((void**)&xg,    g_xg);
    cudaGetSymbolAddress((void**)&z,     g_z);
    cudaGetSymbolAddress((void**)&h,     g_h);
    cudaGetSymbolAddress((void**)&g,     g_g);
    cudaGetSymbolAddress((void**)&adst,  g_adst);
    cudaGetSymbolAddress((void**)&ws1ab, g_ws1ab);
    cudaGetSymbolAddress((void**)&hf,    g_hf);
    cudaGetSymbolAddress((void**)&hs,    g_hs);

    const int SM_GEMM = (2 * 32 * 256) * 4;                    // 65536
    const int SM_H    = KH_SMEM_BYTES;                         // 64640
    cudaFuncSetAttribute(k_irrep,   cudaFuncAttributeMaxDynamicSharedMemorySize, SM_IRREP_MMA);
    cudaFuncSetAttribute(k_gemm256, cudaFuncAttributeMaxDynamicSharedMemorySize, SM_GEMM);
    cudaFuncSetAttribute(k_h,       cudaFuncAttributeMaxDynamicSharedMemorySize, SM_H);
    cudaFuncSetAttribute(k_ws,      cudaFuncAttributeMaxDynamicSharedMemorySize, SM_WS);

    const int gIr = (N + 31) / 32;
    const int gEl = (N * 128 + 255) / 256;

    // Fork a side stream into the capture for the independent gate/nd branch.
    cudaStream_t s1;
    cudaEvent_t evFork, evJoin;
    cudaStreamCreateWithFlags(&s1, cudaStreamNonBlocking);
    cudaEventCreateWithFlags(&evFork, cudaEventDisableTiming);
    cudaEventCreateWithFlags(&evJoin, cudaEventDisableTiming);
    cudaEventRecord(evFork, 0);
    cudaStreamWaitEvent(s1, evFork, 0);

    // Branch B (side stream): gate path + nd irrep (needs only x)
    k_znorm<<<gEl, 256, 0, s1>>>(x, z, N);
    k_gemm256<<<gIr, 256, SM_GEMM, s1>>>(z, W_g1, b_g1, h, N, 1);
    k_gemm256<<<gIr, 256, SM_GEMM, s1>>>(h, W_g2, b_g2, g, N, 0);
    k_xg<<<gEl, 256, 0, s1>>>(x, g, xg, N);
    k_irrep<<<gIr, 256, SM_IRREP_MMA, s1>>>(xg, W_nd0, b_nd0, W_nd1, selfx, acc, nullptr, N);
    cudaEventRecord(evJoin, s1);

    // Branch A (main stream): pre irrep -> adst -> k_h
    k_irrep<<<gIr, 256, SM_IRREP_MMA>>>(x, W_pre0, b_pre0, W_pre1, pre, nullptr, nullptr, N);
    k_prep<<<16, 256>>>(W_s1, ws1ab);
    k_adst<<<(N + 7) / 8, 256>>>(pre, ws1ab, adst, N);
    k_h<<<(E + 63) / 64, 256, SM_H>>>(pre, adst, edge_attr, edge_idx, W_s1, W_f1, hf, hs, E);

    // Join, then edge scatter + output irrep on main stream
    cudaStreamWaitEvent(0, evJoin, 0);
    k_ws<<<(E + 63) / 64, 512, SM_WS>>>(hf, hs, W_f2, W_s2, selfx, edge_sh,
                                        edge_idx, acc, E);
    k_irrep<<<gIr, 256, SM_IRREP_MMA>>>(acc, W_o0, b_o0, W_o1, out, nullptr, x, N);
    // Note: s1/evFork/evJoin intentionally not destroyed while capture may be
    // active (forked-stream destruction mid-capture is undefined); the harness
    // calls kernel_launch only a handful of times, so the host-side leak is
    // bounded and no device memory is involved.
}